// round 1
// baseline (speedup 1.0000x reference)
#include <cuda_runtime.h>
#include <math.h>

#define SEQ     4096
#define HIDDEN  2048
#define NHEADS  16
#define HDIM    128

// ---------------- scratch (no allocations allowed) ----------------
__device__ float g_Q[SEQ * HIDDEN];
__device__ float g_K[SEQ * HIDDEN];
__device__ float g_V[SEQ * HIDDEN];
__device__ float g_C[SEQ * HIDDEN];

// =================================================================
// SGEMM (NT):  C[M,N] = A[M,K] * B[N,K]^T   (both row-major, K-major)
// 128x128 block tile, BK=8, 256 threads, 8x8 per-thread microtile.
// =================================================================
__global__ __launch_bounds__(256) void sgemm_nt(const float* __restrict__ A,
                                                const float* __restrict__ B,
                                                float* __restrict__ C,
                                                int M, int N, int K)
{
    __shared__ float As[8][128];
    __shared__ float Bs[8][128];

    const int bm  = blockIdx.y * 128;
    const int bn  = blockIdx.x * 128;
    const int tid = threadIdx.x;
    const int tr  = tid >> 4;        // 0..15
    const int tc  = tid & 15;        // 0..15
    const int lRow = tid >> 1;       // 0..127
    const int lCol = (tid & 1) << 2; // 0 or 4

    const float* Ag = A + (size_t)(bm + lRow) * K + lCol;
    const float* Bg = B + (size_t)(bn + lRow) * K + lCol;

    float acc[8][8];
#pragma unroll
    for (int i = 0; i < 8; i++)
#pragma unroll
        for (int j = 0; j < 8; j++) acc[i][j] = 0.0f;

    for (int k0 = 0; k0 < K; k0 += 8) {
        float4 av = *reinterpret_cast<const float4*>(Ag + k0);
        float4 bv = *reinterpret_cast<const float4*>(Bg + k0);
        As[lCol + 0][lRow] = av.x;
        As[lCol + 1][lRow] = av.y;
        As[lCol + 2][lRow] = av.z;
        As[lCol + 3][lRow] = av.w;
        Bs[lCol + 0][lRow] = bv.x;
        Bs[lCol + 1][lRow] = bv.y;
        Bs[lCol + 2][lRow] = bv.z;
        Bs[lCol + 3][lRow] = bv.w;
        __syncthreads();

#pragma unroll
        for (int kk = 0; kk < 8; kk++) {
            float a[8], b[8];
            *reinterpret_cast<float4*>(&a[0]) = *reinterpret_cast<const float4*>(&As[kk][tr * 8]);
            *reinterpret_cast<float4*>(&a[4]) = *reinterpret_cast<const float4*>(&As[kk][tr * 8 + 4]);
            *reinterpret_cast<float4*>(&b[0]) = *reinterpret_cast<const float4*>(&Bs[kk][tc * 8]);
            *reinterpret_cast<float4*>(&b[4]) = *reinterpret_cast<const float4*>(&Bs[kk][tc * 8 + 4]);
#pragma unroll
            for (int i = 0; i < 8; i++)
#pragma unroll
                for (int j = 0; j < 8; j++) acc[i][j] += a[i] * b[j];
        }
        __syncthreads();
    }

#pragma unroll
    for (int i = 0; i < 8; i++) {
        float* Cp = C + (size_t)(bm + tr * 8 + i) * N + bn + tc * 8;
        float4 v0 = make_float4(acc[i][0], acc[i][1], acc[i][2], acc[i][3]);
        float4 v1 = make_float4(acc[i][4], acc[i][5], acc[i][6], acc[i][7]);
        *reinterpret_cast<float4*>(Cp)     = v0;
        *reinterpret_cast<float4*>(Cp + 4) = v1;
    }
}

// =================================================================
// RoPE applied in place to Q and K. One thread handles the (i, i+64)
// pair for one (s, head), for both Q and K.
// =================================================================
__global__ void rope_kernel(float* __restrict__ Q, float* __restrict__ K)
{
    int idx = blockIdx.x * blockDim.x + threadIdx.x;   // over SEQ * HIDDEN/2
    if (idx >= SEQ * (HIDDEN / 2)) return;
    int s    = idx / (HIDDEN / 2);
    int r    = idx % (HIDDEN / 2);
    int head = r / 64;
    int i    = r % 64;

    double e    = (double)(2 * i) / 128.0;
    float  finv = (float)pow(10000.0, -e);
    float  ang  = (float)s * finv;          // f32 product, matching reference rounding
    double sn, cs;
    sincos((double)ang, &sn, &cs);
    float c = (float)cs, sv = (float)sn;

    int base = s * HIDDEN + head * HDIM + i;
    {
        float x1 = Q[base], x2 = Q[base + 64];
        Q[base]      = x1 * c - x2 * sv;
        Q[base + 64] = x2 * c + x1 * sv;
    }
    {
        float x1 = K[base], x2 = K[base + 64];
        K[base]      = x1 * c - x2 * sv;
        K[base + 64] = x2 * c + x1 * sv;
    }
}

// =================================================================
// Flash attention, fp32, causal.  Grid: (64 qblocks, 16 heads).
// Block: 256 threads. BQ=BK=64, D=128.
// Thread (tr,tc): tr=tid/16, tc=tid%16.
//   S-gemm: 4x4 microtile  -> rows tr*4+i, cols tc*4+j
//   O-gemm: 4x8 microtile  -> rows tr*4+i, cols tc*8+j
// =================================================================
#define BQ 64
#define BKEY 64
#define QSTR 129   // padded stride to avoid bank conflicts (scalar stores)
#define KSTR 129
#define VSTR 132   // float4-aligned padded stride
#define PSTR 65

__global__ __launch_bounds__(256, 1) void attn_kernel(const float* __restrict__ Q,
                                                      const float* __restrict__ K,
                                                      const float* __restrict__ V,
                                                      float* __restrict__ CTX)
{
    extern __shared__ float smem[];
    float* sQ = smem;                    // BQ   * QSTR
    float* sK = sQ + BQ * QSTR;          // BKEY * KSTR
    float* sV = sK + BKEY * KSTR;        // BKEY * VSTR  (16B-aligned base)
    float* sP = sV + BKEY * VSTR;        // BQ   * PSTR

    const int qb  = (int)(gridDim.x - 1) - (int)blockIdx.x;  // longest-first
    const int h   = blockIdx.y;
    const int tid = threadIdx.x;
    const int tr  = tid >> 4;   // 0..15
    const int tc  = tid & 15;   // 0..15

    // ---- load Q tile (64 x 128) ----
    const float* Qg = Q + (size_t)(qb * BQ) * HIDDEN + h * HDIM;
    for (int i = tid; i < BQ * 32; i += 256) {
        int row = i >> 5, c4 = i & 31;
        float4 v = *reinterpret_cast<const float4*>(Qg + (size_t)row * HIDDEN + c4 * 4);
        float* d = sQ + row * QSTR + c4 * 4;
        d[0] = v.x; d[1] = v.y; d[2] = v.z; d[3] = v.w;
    }

    float m_i[4], l_i[4], acc[4][8];
#pragma unroll
    for (int i = 0; i < 4; i++) {
        m_i[i] = -1e30f;
        l_i[i] = 0.0f;
#pragma unroll
        for (int j = 0; j < 8; j++) acc[i][j] = 0.0f;
    }
    const float scale = 0.08838834764831845f;  // 1/sqrt(128)

    for (int kb = 0; kb <= qb; kb++) {
        // ---- load K, V tiles ----
        const float* Kg = K + (size_t)(kb * BKEY) * HIDDEN + h * HDIM;
        const float* Vg = V + (size_t)(kb * BKEY) * HIDDEN + h * HDIM;
        for (int i = tid; i < BKEY * 32; i += 256) {
            int row = i >> 5, c4 = i & 31;
            float4 v = *reinterpret_cast<const float4*>(Kg + (size_t)row * HIDDEN + c4 * 4);
            float* d = sK + row * KSTR + c4 * 4;
            d[0] = v.x; d[1] = v.y; d[2] = v.z; d[3] = v.w;
        }
        for (int i = tid; i < BKEY * 32; i += 256) {
            int row = i >> 5, c4 = i & 31;
            float4 v = *reinterpret_cast<const float4*>(Vg + (size_t)row * HIDDEN + c4 * 4);
            *reinterpret_cast<float4*>(sV + row * VSTR + c4 * 4) = v;
        }
        __syncthreads();

        // ---- S = Q K^T (4x4 microtile) ----
        float s_acc[4][4];
#pragma unroll
        for (int i = 0; i < 4; i++)
#pragma unroll
            for (int j = 0; j < 4; j++) s_acc[i][j] = 0.0f;

#pragma unroll 8
        for (int k = 0; k < HDIM; k++) {
            float a0 = sQ[(tr * 4 + 0) * QSTR + k];
            float a1 = sQ[(tr * 4 + 1) * QSTR + k];
            float a2 = sQ[(tr * 4 + 2) * QSTR + k];
            float a3 = sQ[(tr * 4 + 3) * QSTR + k];
            float b0 = sK[(tc * 4 + 0) * KSTR + k];
            float b1 = sK[(tc * 4 + 1) * KSTR + k];
            float b2 = sK[(tc * 4 + 2) * KSTR + k];
            float b3 = sK[(tc * 4 + 3) * KSTR + k];
            s_acc[0][0] += a0 * b0; s_acc[0][1] += a0 * b1; s_acc[0][2] += a0 * b2; s_acc[0][3] += a0 * b3;
            s_acc[1][0] += a1 * b0; s_acc[1][1] += a1 * b1; s_acc[1][2] += a1 * b2; s_acc[1][3] += a1 * b3;
            s_acc[2][0] += a2 * b0; s_acc[2][1] += a2 * b1; s_acc[2][2] += a2 * b2; s_acc[2][3] += a2 * b3;
            s_acc[3][0] += a3 * b0; s_acc[3][1] += a3 * b1; s_acc[3][2] += a3 * b2; s_acc[3][3] += a3 * b3;
        }

        // ---- online softmax per row (rows owned by 16 lanes tc=0..15) ----
        const bool diag = (kb == qb);
#pragma unroll
        for (int i = 0; i < 4; i++) {
            float rowmax = -1e30f;
#pragma unroll
            for (int j = 0; j < 4; j++) {
                float svv = s_acc[i][j] * scale;
                if (diag && (tc * 4 + j) > (tr * 4 + i)) svv = -1e30f;
                s_acc[i][j] = svv;
                rowmax = fmaxf(rowmax, svv);
            }
#pragma unroll
            for (int off = 8; off > 0; off >>= 1)
                rowmax = fmaxf(rowmax, __shfl_xor_sync(0xffffffffu, rowmax, off));

            float mnew = fmaxf(m_i[i], rowmax);
            float corr = __expf(m_i[i] - mnew);
            m_i[i] = mnew;

            float rsum = 0.0f;
#pragma unroll
            for (int j = 0; j < 4; j++) {
                float p = __expf(s_acc[i][j] - mnew);
                s_acc[i][j] = p;
                rsum += p;
            }
#pragma unroll
            for (int off = 8; off > 0; off >>= 1)
                rsum += __shfl_xor_sync(0xffffffffu, rsum, off);

            l_i[i] = l_i[i] * corr + rsum;
#pragma unroll
            for (int j = 0; j < 8; j++) acc[i][j] *= corr;
        }

        // ---- write P to shared ----
#pragma unroll
        for (int i = 0; i < 4; i++)
#pragma unroll
            for (int j = 0; j < 4; j++)
                sP[(tr * 4 + i) * PSTR + tc * 4 + j] = s_acc[i][j];
        __syncthreads();

        // ---- O += P V (4x8 microtile) ----
#pragma unroll 4
        for (int c = 0; c < BKEY; c++) {
            float p0 = sP[(tr * 4 + 0) * PSTR + c];
            float p1 = sP[(tr * 4 + 1) * PSTR + c];
            float p2 = sP[(tr * 4 + 2) * PSTR + c];
            float p3 = sP[(tr * 4 + 3) * PSTR + c];
            float4 v0 = *reinterpret_cast<const float4*>(sV + c * VSTR + tc * 8);
            float4 v1 = *reinterpret_cast<const float4*>(sV + c * VSTR + tc * 8 + 4);
            acc[0][0] += p0 * v0.x; acc[0][1] += p0 * v0.y; acc[0][2] += p0 * v0.z; acc[0][3] += p0 * v0.w;
            acc[0][4] += p0 * v1.x; acc[0][5] += p0 * v1.y; acc[0][6] += p0 * v1.z; acc[0][7] += p0 * v1.w;
            acc[1][0] += p1 * v0.x; acc[1][1] += p1 * v0.y; acc[1][2] += p1 * v0.z; acc[1][3] += p1 * v0.w;
            acc[1][4] += p1 * v1.x; acc[1][5] += p1 * v1.y; acc[1][6] += p1 * v1.z; acc[1][7] += p1 * v1.w;
            acc[2][0] += p2 * v0.x; acc[2][1] += p2 * v0.y; acc[2][2] += p2 * v0.z; acc[2][3] += p2 * v0.w;
            acc[2][4] += p2 * v1.x; acc[2][5] += p2 * v1.y; acc[2][6] += p2 * v1.z; acc[2][7] += p2 * v1.w;
            acc[3][0] += p3 * v0.x; acc[3][1] += p3 * v0.y; acc[3][2] += p3 * v0.z; acc[3][3] += p3 * v0.w;
            acc[3][4] += p3 * v1.x; acc[3][5] += p3 * v1.y; acc[3][6] += p3 * v1.z; acc[3][7] += p3 * v1.w;
        }
        __syncthreads();
    }

    // ---- epilogue: normalize and store ----
    float* Cg = CTX + (size_t)(qb * BQ) * HIDDEN + h * HDIM;
#pragma unroll
    for (int i = 0; i < 4; i++) {
        float inv = 1.0f / l_i[i];
        float* p  = Cg + (size_t)(tr * 4 + i) * HIDDEN + tc * 8;
        float4 v0 = make_float4(acc[i][0] * inv, acc[i][1] * inv, acc[i][2] * inv, acc[i][3] * inv);
        float4 v1 = make_float4(acc[i][4] * inv, acc[i][5] * inv, acc[i][6] * inv, acc[i][7] * inv);
        *reinterpret_cast<float4*>(p)     = v0;
        *reinterpret_cast<float4*>(p + 4) = v1;
    }
}

// =================================================================
// Launcher
// =================================================================
extern "C" void kernel_launch(void* const* d_in, const int* in_sizes, int n_in,
                              void* d_out, int out_size)
{
    const float* X  = (const float*)d_in[0];
    const float* Wq = (const float*)d_in[1];
    const float* Wk = (const float*)d_in[2];
    const float* Wv = (const float*)d_in[3];
    const float* Wo = (const float*)d_in[4];
    float* out = (float*)d_out;

    float *q, *k, *v, *ctx;
    cudaGetSymbolAddress((void**)&q,   g_Q);
    cudaGetSymbolAddress((void**)&k,   g_K);
    cudaGetSymbolAddress((void**)&v,   g_V);
    cudaGetSymbolAddress((void**)&ctx, g_C);

    dim3 ggrid(HIDDEN / 128, SEQ / 128);   // (16, 32)
    sgemm_nt<<<ggrid, 256>>>(X, Wq, q, SEQ, HIDDEN, HIDDEN);
    sgemm_nt<<<ggrid, 256>>>(X, Wk, k, SEQ, HIDDEN, HIDDEN);
    sgemm_nt<<<ggrid, 256>>>(X, Wv, v, SEQ, HIDDEN, HIDDEN);

    int rope_threads = SEQ * (HIDDEN / 2);
    rope_kernel<<<(rope_threads + 255) / 256, 256>>>(q, k);

    size_t attn_smem = (size_t)(BQ * QSTR + BKEY * KSTR + BKEY * VSTR + BQ * PSTR) * sizeof(float);
    cudaFuncSetAttribute(attn_kernel, cudaFuncAttributeMaxDynamicSharedMemorySize, (int)attn_smem);
    dim3 agrid(SEQ / BQ, NHEADS);          // (64, 16)
    attn_kernel<<<agrid, 256, attn_smem>>>(q, k, v, ctx);

    sgemm_nt<<<ggrid, 256>>>(ctx, Wo, out, SEQ, HIDDEN, HIDDEN);
}

// round 3
// speedup vs baseline: 1.3240x; 1.3240x over previous
#include <cuda_runtime.h>
#include <cuda_bf16.h>
#include <mma.h>
#include <math.h>
#include <cstdint>

using namespace nvcuda;

#define SEQ     4096
#define HIDDEN  2048
#define NHEADS  16
#define HDIM    128

// ---------------- scratch (no allocations allowed) ----------------
__device__ float g_Q[SEQ * HIDDEN];
__device__ float g_K[SEQ * HIDDEN];
__device__ float g_V[SEQ * HIDDEN];
__device__ float g_C[SEQ * HIDDEN];

// =================================================================
// WMMA bf16x3-split GEMM (NT): C[M,N] = A[M,K] * B[N,K]^T, fp32 in/out.
// 128x128 CTA tile, BK=32, 8 warps (2x4), warp tile 64x32 (4x2 wmma
// 16x16x16 tiles). hi*hi + hi*lo + lo*hi with fp32 accumulators.
// Double-buffered smem; fp32->bf16 hi/lo split done on the smem store.
// =================================================================
#define GBM 128
#define GBN 128
#define GBK 32
#define SSTR 40                       // smem row stride in halves (80B, 16B-aligned rows)
#define TILE_H (128 * SSTR)           // 5120 halves per tile
#define BUF_H  (4 * TILE_H)           // Ah, Al, Bh, Bl
#define GEMM_SMEM_BYTES (2 * BUF_H * 2)  // 81920 bytes

__device__ __forceinline__ void split_f4(float4 v, uint2& hi, uint2& lo)
{
    __nv_bfloat16 hx = __float2bfloat16_rn(v.x);
    __nv_bfloat16 hy = __float2bfloat16_rn(v.y);
    __nv_bfloat16 hz = __float2bfloat16_rn(v.z);
    __nv_bfloat16 hw = __float2bfloat16_rn(v.w);
    __nv_bfloat16 lx = __float2bfloat16_rn(v.x - __bfloat162float(hx));
    __nv_bfloat16 ly = __float2bfloat16_rn(v.y - __bfloat162float(hy));
    __nv_bfloat16 lz = __float2bfloat16_rn(v.z - __bfloat162float(hz));
    __nv_bfloat16 lw = __float2bfloat16_rn(v.w - __bfloat162float(hw));
    __nv_bfloat162 h01 = __halves2bfloat162(hx, hy);
    __nv_bfloat162 h23 = __halves2bfloat162(hz, hw);
    __nv_bfloat162 l01 = __halves2bfloat162(lx, ly);
    __nv_bfloat162 l23 = __halves2bfloat162(lz, lw);
    hi = make_uint2(*(uint32_t*)&h01, *(uint32_t*)&h23);
    lo = make_uint2(*(uint32_t*)&l01, *(uint32_t*)&l23);
}

__global__ __launch_bounds__(256, 1) void gemm_wmma(const float* __restrict__ A,
                                                    const float* __restrict__ B,
                                                    float* __restrict__ C,
                                                    int M, int N, int K)
{
    extern __shared__ __nv_bfloat16 sh[];

    const int tid = threadIdx.x;
    const int wid = tid >> 5;
    const int wm  = wid & 1;          // 0..1 over M
    const int wn  = wid >> 1;         // 0..3 over N
    const int bm  = blockIdx.y * GBM;
    const int bn  = blockIdx.x * GBN;

    typedef wmma::fragment<wmma::matrix_a, 16, 16, 16, __nv_bfloat16, wmma::row_major> AFrag;
    typedef wmma::fragment<wmma::matrix_b, 16, 16, 16, __nv_bfloat16, wmma::col_major> BFrag;
    typedef wmma::fragment<wmma::accumulator, 16, 16, 16, float> CFrag;

    CFrag c[4][2];
#pragma unroll
    for (int mi = 0; mi < 4; mi++)
#pragma unroll
        for (int ni = 0; ni < 2; ni++) wmma::fill_fragment(c[mi][ni], 0.0f);

    // per-thread global-load mapping: 1024 float4 per matrix tile, 4 each
    float4 regA[4], regB[4];

    const int ntile = K / GBK;        // 64

    // ---- prologue: load k-tile 0, store to buffer 0 ----
#pragma unroll
    for (int t = 0; t < 4; t++) {
        int idx = tid + 256 * t;
        int row = idx >> 3, c4 = idx & 7;
        regA[t] = *reinterpret_cast<const float4*>(A + (size_t)(bm + row) * K + c4 * 4);
        regB[t] = *reinterpret_cast<const float4*>(B + (size_t)(bn + row) * K + c4 * 4);
    }
    {
        __nv_bfloat16* Ah = sh;
        __nv_bfloat16* Al = sh + TILE_H;
        __nv_bfloat16* Bh = sh + 2 * TILE_H;
        __nv_bfloat16* Bl = sh + 3 * TILE_H;
#pragma unroll
        for (int t = 0; t < 4; t++) {
            int idx = tid + 256 * t;
            int row = idx >> 3, c4 = idx & 7;
            uint2 hi, lo;
            split_f4(regA[t], hi, lo);
            *reinterpret_cast<uint2*>(Ah + row * SSTR + c4 * 4) = hi;
            *reinterpret_cast<uint2*>(Al + row * SSTR + c4 * 4) = lo;
            split_f4(regB[t], hi, lo);
            *reinterpret_cast<uint2*>(Bh + row * SSTR + c4 * 4) = hi;
            *reinterpret_cast<uint2*>(Bl + row * SSTR + c4 * 4) = lo;
        }
    }
    __syncthreads();

    for (int it = 0; it < ntile; it++) {
        // ---- issue next global loads (latency hidden by compute below) ----
        if (it + 1 < ntile) {
            const int k0 = (it + 1) * GBK;
#pragma unroll
            for (int t = 0; t < 4; t++) {
                int idx = tid + 256 * t;
                int row = idx >> 3, c4 = idx & 7;
                regA[t] = *reinterpret_cast<const float4*>(A + (size_t)(bm + row) * K + k0 + c4 * 4);
                regB[t] = *reinterpret_cast<const float4*>(B + (size_t)(bn + row) * K + k0 + c4 * 4);
            }
        }

        // ---- compute from current buffer ----
        {
            const __nv_bfloat16* base = sh + (it & 1) * BUF_H;
            const __nv_bfloat16* Ah = base;
            const __nv_bfloat16* Al = base + TILE_H;
            const __nv_bfloat16* Bh = base + 2 * TILE_H;
            const __nv_bfloat16* Bl = base + 3 * TILE_H;
#pragma unroll
            for (int ks = 0; ks < GBK; ks += 16) {
                AFrag a_h[4], a_l[4];
                BFrag b_h[2], b_l[2];
#pragma unroll
                for (int mi = 0; mi < 4; mi++) {
                    int r = (wm * 64 + mi * 16) * SSTR + ks;
                    wmma::load_matrix_sync(a_h[mi], Ah + r, SSTR);
                    wmma::load_matrix_sync(a_l[mi], Al + r, SSTR);
                }
#pragma unroll
                for (int ni = 0; ni < 2; ni++) {
                    int r = (wn * 32 + ni * 16) * SSTR + ks;
                    wmma::load_matrix_sync(b_h[ni], Bh + r, SSTR);
                    wmma::load_matrix_sync(b_l[ni], Bl + r, SSTR);
                }
#pragma unroll
                for (int mi = 0; mi < 4; mi++)
#pragma unroll
                    for (int ni = 0; ni < 2; ni++) {
                        wmma::mma_sync(c[mi][ni], a_h[mi], b_h[ni], c[mi][ni]);
                        wmma::mma_sync(c[mi][ni], a_h[mi], b_l[ni], c[mi][ni]);
                        wmma::mma_sync(c[mi][ni], a_l[mi], b_h[ni], c[mi][ni]);
                    }
            }
        }

        // ---- convert+store next k-tile into the other buffer ----
        if (it + 1 < ntile) {
            __nv_bfloat16* base = sh + ((it + 1) & 1) * BUF_H;
            __nv_bfloat16* Ah = base;
            __nv_bfloat16* Al = base + TILE_H;
            __nv_bfloat16* Bh = base + 2 * TILE_H;
            __nv_bfloat16* Bl = base + 3 * TILE_H;
#pragma unroll
            for (int t = 0; t < 4; t++) {
                int idx = tid + 256 * t;
                int row = idx >> 3, c4 = idx & 7;
                uint2 hi, lo;
                split_f4(regA[t], hi, lo);
                *reinterpret_cast<uint2*>(Ah + row * SSTR + c4 * 4) = hi;
                *reinterpret_cast<uint2*>(Al + row * SSTR + c4 * 4) = lo;
                split_f4(regB[t], hi, lo);
                *reinterpret_cast<uint2*>(Bh + row * SSTR + c4 * 4) = hi;
                *reinterpret_cast<uint2*>(Bl + row * SSTR + c4 * 4) = lo;
            }
        }
        __syncthreads();
    }

    // ---- epilogue ----
#pragma unroll
    for (int mi = 0; mi < 4; mi++)
#pragma unroll
        for (int ni = 0; ni < 2; ni++) {
            int r = bm + wm * 64 + mi * 16;
            int cc = bn + wn * 32 + ni * 16;
            wmma::store_matrix_sync(C + (size_t)r * N + cc, c[mi][ni], N, wmma::mem_row_major);
        }
}

// =================================================================
// RoPE applied in place to Q and K.
// =================================================================
__global__ void rope_kernel(float* __restrict__ Q, float* __restrict__ K)
{
    int idx = blockIdx.x * blockDim.x + threadIdx.x;
    if (idx >= SEQ * (HIDDEN / 2)) return;
    int s    = idx / (HIDDEN / 2);
    int r    = idx % (HIDDEN / 2);
    int head = r / 64;
    int i    = r % 64;

    double e    = (double)(2 * i) / 128.0;
    float  finv = (float)pow(10000.0, -e);
    float  ang  = (float)s * finv;
    double sn, cs;
    sincos((double)ang, &sn, &cs);
    float c = (float)cs, sv = (float)sn;

    int base = s * HIDDEN + head * HDIM + i;
    {
        float x1 = Q[base], x2 = Q[base + 64];
        Q[base]      = x1 * c - x2 * sv;
        Q[base + 64] = x2 * c + x1 * sv;
    }
    {
        float x1 = K[base], x2 = K[base + 64];
        K[base]      = x1 * c - x2 * sv;
        K[base + 64] = x2 * c + x1 * sv;
    }
}

// =================================================================
// Flash attention, fp32, causal (R1 passing version).
// =================================================================
#define BQ 64
#define BKEY 64
#define QSTR 129
#define KSTR 129
#define VSTR 132
#define PSTR 65

__global__ __launch_bounds__(256, 1) void attn_kernel(const float* __restrict__ Q,
                                                      const float* __restrict__ K,
                                                      const float* __restrict__ V,
                                                      float* __restrict__ CTX)
{
    extern __shared__ float smemf[];
    float* sQ = smemf;
    float* sK = sQ + BQ * QSTR;
    float* sV = sK + BKEY * KSTR;
    float* sP = sV + BKEY * VSTR;

    const int qb  = (int)(gridDim.x - 1) - (int)blockIdx.x;
    const int h   = blockIdx.y;
    const int tid = threadIdx.x;
    const int tr  = tid >> 4;
    const int tc  = tid & 15;

    const float* Qg = Q + (size_t)(qb * BQ) * HIDDEN + h * HDIM;
    for (int i = tid; i < BQ * 32; i += 256) {
        int row = i >> 5, c4 = i & 31;
        float4 v = *reinterpret_cast<const float4*>(Qg + (size_t)row * HIDDEN + c4 * 4);
        float* d = sQ + row * QSTR + c4 * 4;
        d[0] = v.x; d[1] = v.y; d[2] = v.z; d[3] = v.w;
    }

    float m_i[4], l_i[4], acc[4][8];
#pragma unroll
    for (int i = 0; i < 4; i++) {
        m_i[i] = -1e30f;
        l_i[i] = 0.0f;
#pragma unroll
        for (int j = 0; j < 8; j++) acc[i][j] = 0.0f;
    }
    const float scale = 0.08838834764831845f;

    for (int kb = 0; kb <= qb; kb++) {
        const float* Kg = K + (size_t)(kb * BKEY) * HIDDEN + h * HDIM;
        const float* Vg = V + (size_t)(kb * BKEY) * HIDDEN + h * HDIM;
        for (int i = tid; i < BKEY * 32; i += 256) {
            int row = i >> 5, c4 = i & 31;
            float4 v = *reinterpret_cast<const float4*>(Kg + (size_t)row * HIDDEN + c4 * 4);
            float* d = sK + row * KSTR + c4 * 4;
            d[0] = v.x; d[1] = v.y; d[2] = v.z; d[3] = v.w;
        }
        for (int i = tid; i < BKEY * 32; i += 256) {
            int row = i >> 5, c4 = i & 31;
            float4 v = *reinterpret_cast<const float4*>(Vg + (size_t)row * HIDDEN + c4 * 4);
            *reinterpret_cast<float4*>(sV + row * VSTR + c4 * 4) = v;
        }
        __syncthreads();

        float s_acc[4][4];
#pragma unroll
        for (int i = 0; i < 4; i++)
#pragma unroll
            for (int j = 0; j < 4; j++) s_acc[i][j] = 0.0f;

#pragma unroll 8
        for (int k = 0; k < HDIM; k++) {
            float a0 = sQ[(tr * 4 + 0) * QSTR + k];
            float a1 = sQ[(tr * 4 + 1) * QSTR + k];
            float a2 = sQ[(tr * 4 + 2) * QSTR + k];
            float a3 = sQ[(tr * 4 + 3) * QSTR + k];
            float b0 = sK[(tc * 4 + 0) * KSTR + k];
            float b1 = sK[(tc * 4 + 1) * KSTR + k];
            float b2 = sK[(tc * 4 + 2) * KSTR + k];
            float b3 = sK[(tc * 4 + 3) * KSTR + k];
            s_acc[0][0] += a0 * b0; s_acc[0][1] += a0 * b1; s_acc[0][2] += a0 * b2; s_acc[0][3] += a0 * b3;
            s_acc[1][0] += a1 * b0; s_acc[1][1] += a1 * b1; s_acc[1][2] += a1 * b2; s_acc[1][3] += a1 * b3;
            s_acc[2][0] += a2 * b0; s_acc[2][1] += a2 * b1; s_acc[2][2] += a2 * b2; s_acc[2][3] += a2 * b3;
            s_acc[3][0] += a3 * b0; s_acc[3][1] += a3 * b1; s_acc[3][2] += a3 * b2; s_acc[3][3] += a3 * b3;
        }

        const bool diag = (kb == qb);
#pragma unroll
        for (int i = 0; i < 4; i++) {
            float rowmax = -1e30f;
#pragma unroll
            for (int j = 0; j < 4; j++) {
                float svv = s_acc[i][j] * scale;
                if (diag && (tc * 4 + j) > (tr * 4 + i)) svv = -1e30f;
                s_acc[i][j] = svv;
                rowmax = fmaxf(rowmax, svv);
            }
#pragma unroll
            for (int off = 8; off > 0; off >>= 1)
                rowmax = fmaxf(rowmax, __shfl_xor_sync(0xffffffffu, rowmax, off));

            float mnew = fmaxf(m_i[i], rowmax);
            float corr = __expf(m_i[i] - mnew);
            m_i[i] = mnew;

            float rsum = 0.0f;
#pragma unroll
            for (int j = 0; j < 4; j++) {
                float p = __expf(s_acc[i][j] - mnew);
                s_acc[i][j] = p;
                rsum += p;
            }
#pragma unroll
            for (int off = 8; off > 0; off >>= 1)
                rsum += __shfl_xor_sync(0xffffffffu, rsum, off);

            l_i[i] = l_i[i] * corr + rsum;
#pragma unroll
            for (int j = 0; j < 8; j++) acc[i][j] *= corr;
        }

#pragma unroll
        for (int i = 0; i < 4; i++)
#pragma unroll
            for (int j = 0; j < 4; j++)
                sP[(tr * 4 + i) * PSTR + tc * 4 + j] = s_acc[i][j];
        __syncthreads();

#pragma unroll 4
        for (int c = 0; c < BKEY; c++) {
            float p0 = sP[(tr * 4 + 0) * PSTR + c];
            float p1 = sP[(tr * 4 + 1) * PSTR + c];
            float p2 = sP[(tr * 4 + 2) * PSTR + c];
            float p3 = sP[(tr * 4 + 3) * PSTR + c];
            float4 v0 = *reinterpret_cast<const float4*>(sV + c * VSTR + tc * 8);
            float4 v1 = *reinterpret_cast<const float4*>(sV + c * VSTR + tc * 8 + 4);
            acc[0][0] += p0 * v0.x; acc[0][1] += p0 * v0.y; acc[0][2] += p0 * v0.z; acc[0][3] += p0 * v0.w;
            acc[0][4] += p0 * v1.x; acc[0][5] += p0 * v1.y; acc[0][6] += p0 * v1.z; acc[0][7] += p0 * v1.w;
            acc[1][0] += p1 * v0.x; acc[1][1] += p1 * v0.y; acc[1][2] += p1 * v0.z; acc[1][3] += p1 * v0.w;
            acc[1][4] += p1 * v1.x; acc[1][5] += p1 * v1.y; acc[1][6] += p1 * v1.z; acc[1][7] += p1 * v1.w;
            acc[2][0] += p2 * v0.x; acc[2][1] += p2 * v0.y; acc[2][2] += p2 * v0.z; acc[2][3] += p2 * v0.w;
            acc[2][4] += p2 * v1.x; acc[2][5] += p2 * v1.y; acc[2][6] += p2 * v1.z; acc[2][7] += p2 * v1.w;
            acc[3][0] += p3 * v0.x; acc[3][1] += p3 * v0.y; acc[3][2] += p3 * v0.z; acc[3][3] += p3 * v0.w;
            acc[3][4] += p3 * v1.x; acc[3][5] += p3 * v1.y; acc[3][6] += p3 * v1.z; acc[3][7] += p3 * v1.w;
        }
        __syncthreads();
    }

    float* Cg = CTX + (size_t)(qb * BQ) * HIDDEN + h * HDIM;
#pragma unroll
    for (int i = 0; i < 4; i++) {
        float inv = 1.0f / l_i[i];
        float* p  = Cg + (size_t)(tr * 4 + i) * HIDDEN + tc * 8;
        float4 v0 = make_float4(acc[i][0] * inv, acc[i][1] * inv, acc[i][2] * inv, acc[i][3] * inv);
        float4 v1 = make_float4(acc[i][4] * inv, acc[i][5] * inv, acc[i][6] * inv, acc[i][7] * inv);
        *reinterpret_cast<float4*>(p)     = v0;
        *reinterpret_cast<float4*>(p + 4) = v1;
    }
}

// =================================================================
// Launcher
// =================================================================
extern "C" void kernel_launch(void* const* d_in, const int* in_sizes, int n_in,
                              void* d_out, int out_size)
{
    const float* X  = (const float*)d_in[0];
    const float* Wq = (const float*)d_in[1];
    const float* Wk = (const float*)d_in[2];
    const float* Wv = (const float*)d_in[3];
    const float* Wo = (const float*)d_in[4];
    float* out = (float*)d_out;

    float *q, *k, *v, *ctx;
    cudaGetSymbolAddress((void**)&q,   g_Q);
    cudaGetSymbolAddress((void**)&k,   g_K);
    cudaGetSymbolAddress((void**)&v,   g_V);
    cudaGetSymbolAddress((void**)&ctx, g_C);

    cudaFuncSetAttribute(gemm_wmma, cudaFuncAttributeMaxDynamicSharedMemorySize, GEMM_SMEM_BYTES);

    dim3 ggrid(HIDDEN / 128, SEQ / 128);   // (16, 32)
    gemm_wmma<<<ggrid, 256, GEMM_SMEM_BYTES>>>(X, Wq, q, SEQ, HIDDEN, HIDDEN);
    gemm_wmma<<<ggrid, 256, GEMM_SMEM_BYTES>>>(X, Wk, k, SEQ, HIDDEN, HIDDEN);
    gemm_wmma<<<ggrid, 256, GEMM_SMEM_BYTES>>>(X, Wv, v, SEQ, HIDDEN, HIDDEN);

    int rope_threads = SEQ * (HIDDEN / 2);
    rope_kernel<<<(rope_threads + 255) / 256, 256>>>(q, k);

    size_t attn_smem = (size_t)(BQ * QSTR + BKEY * KSTR + BKEY * VSTR + BQ * PSTR) * sizeof(float);
    cudaFuncSetAttribute(attn_kernel, cudaFuncAttributeMaxDynamicSharedMemorySize, (int)attn_smem);
    dim3 agrid(SEQ / BQ, NHEADS);
    attn_kernel<<<agrid, 256, attn_smem>>>(q, k, v, ctx);

    gemm_wmma<<<ggrid, 256, GEMM_SMEM_BYTES>>>(ctx, Wo, out, SEQ, HIDDEN, HIDDEN);
}

// round 5
// speedup vs baseline: 1.8650x; 1.4086x over previous
#include <cuda_runtime.h>
#include <cuda_bf16.h>
#include <mma.h>
#include <math.h>
#include <cstdint>

using namespace nvcuda;

#define SEQ     4096
#define HIDDEN  2048
#define NHEADS  16
#define HDIM    128

// ---------------- scratch (no allocations allowed) ----------------
__device__ float g_Q[SEQ * HIDDEN];
__device__ float g_K[SEQ * HIDDEN];
__device__ float g_V[SEQ * HIDDEN];
__device__ float g_C[SEQ * HIDDEN];

// =================================================================
// Common helpers
// =================================================================
__device__ __forceinline__ uint32_t smem_u32(const void* p) {
    uint32_t a;
    asm("{ .reg .u64 t; cvta.to.shared.u64 t, %1; cvt.u32.u64 %0, t; }" : "=r"(a) : "l"(p));
    return a;
}

#define LDM4(r, addr) \
    asm volatile("ldmatrix.sync.aligned.m8n8.x4.shared.b16 {%0,%1,%2,%3}, [%4];" \
        : "=r"((r)[0]), "=r"((r)[1]), "=r"((r)[2]), "=r"((r)[3]) : "r"(addr))

__device__ __forceinline__ void mma16816(float* c, const uint32_t* a, const uint32_t* b) {
    asm volatile(
        "mma.sync.aligned.m16n8k16.row.col.f32.bf16.bf16.f32 "
        "{%0,%1,%2,%3}, {%4,%5,%6,%7}, {%8,%9}, {%0,%1,%2,%3};"
        : "+f"(c[0]), "+f"(c[1]), "+f"(c[2]), "+f"(c[3])
        : "r"(a[0]), "r"(a[1]), "r"(a[2]), "r"(a[3]), "r"(b[0]), "r"(b[1]));
}

// pack (x0,x1) -> bf16x2 hi, and residual bf16x2 lo
__device__ __forceinline__ void split_pack(float x0, float x1, uint32_t& h, uint32_t& l) {
    uint32_t hh, ll;
    asm("cvt.rn.bf16x2.f32 %0, %1, %2;" : "=r"(hh) : "f"(x1), "f"(x0));
    float h0 = __uint_as_float(hh << 16);
    float h1 = __uint_as_float(hh & 0xffff0000u);
    float r0 = x0 - h0, r1 = x1 - h1;
    asm("cvt.rn.bf16x2.f32 %0, %1, %2;" : "=r"(ll) : "f"(r1), "f"(r0));
    h = hh; l = ll;
}

__device__ __forceinline__ void split_f4(float4 v, uint2& hi, uint2& lo)
{
    __nv_bfloat16 hx = __float2bfloat16_rn(v.x);
    __nv_bfloat16 hy = __float2bfloat16_rn(v.y);
    __nv_bfloat16 hz = __float2bfloat16_rn(v.z);
    __nv_bfloat16 hw = __float2bfloat16_rn(v.w);
    __nv_bfloat16 lx = __float2bfloat16_rn(v.x - __bfloat162float(hx));
    __nv_bfloat16 ly = __float2bfloat16_rn(v.y - __bfloat162float(hy));
    __nv_bfloat16 lz = __float2bfloat16_rn(v.z - __bfloat162float(hz));
    __nv_bfloat16 lw = __float2bfloat16_rn(v.w - __bfloat162float(hw));
    __nv_bfloat162 h01 = __halves2bfloat162(hx, hy);
    __nv_bfloat162 h23 = __halves2bfloat162(hz, hw);
    __nv_bfloat162 l01 = __halves2bfloat162(lx, ly);
    __nv_bfloat162 l23 = __halves2bfloat162(lz, lw);
    hi = make_uint2(*(uint32_t*)&h01, *(uint32_t*)&h23);
    lo = make_uint2(*(uint32_t*)&l01, *(uint32_t*)&l23);
}

// =================================================================
// WMMA bf16x3-split GEMM (NT) — unchanged from R3 (passing).
// =================================================================
#define GBM 128
#define GBN 128
#define GBK 32
#define SSTR 40
#define TILE_H (128 * SSTR)
#define BUF_H  (4 * TILE_H)
#define GEMM_SMEM_BYTES (2 * BUF_H * 2)

__global__ __launch_bounds__(256, 1) void gemm_wmma(const float* __restrict__ A,
                                                    const float* __restrict__ B,
                                                    float* __restrict__ C,
                                                    int M, int N, int K)
{
    extern __shared__ __nv_bfloat16 sh[];

    const int tid = threadIdx.x;
    const int wid = tid >> 5;
    const int wm  = wid & 1;
    const int wn  = wid >> 1;
    const int bm  = blockIdx.y * GBM;
    const int bn  = blockIdx.x * GBN;

    typedef wmma::fragment<wmma::matrix_a, 16, 16, 16, __nv_bfloat16, wmma::row_major> AFrag;
    typedef wmma::fragment<wmma::matrix_b, 16, 16, 16, __nv_bfloat16, wmma::col_major> BFrag;
    typedef wmma::fragment<wmma::accumulator, 16, 16, 16, float> CFrag;

    CFrag c[4][2];
#pragma unroll
    for (int mi = 0; mi < 4; mi++)
#pragma unroll
        for (int ni = 0; ni < 2; ni++) wmma::fill_fragment(c[mi][ni], 0.0f);

    float4 regA[4], regB[4];
    const int ntile = K / GBK;

#pragma unroll
    for (int t = 0; t < 4; t++) {
        int idx = tid + 256 * t;
        int row = idx >> 3, c4 = idx & 7;
        regA[t] = *reinterpret_cast<const float4*>(A + (size_t)(bm + row) * K + c4 * 4);
        regB[t] = *reinterpret_cast<const float4*>(B + (size_t)(bn + row) * K + c4 * 4);
    }
    {
        __nv_bfloat16* Ah = sh;
        __nv_bfloat16* Al = sh + TILE_H;
        __nv_bfloat16* Bh = sh + 2 * TILE_H;
        __nv_bfloat16* Bl = sh + 3 * TILE_H;
#pragma unroll
        for (int t = 0; t < 4; t++) {
            int idx = tid + 256 * t;
            int row = idx >> 3, c4 = idx & 7;
            uint2 hi, lo;
            split_f4(regA[t], hi, lo);
            *reinterpret_cast<uint2*>(Ah + row * SSTR + c4 * 4) = hi;
            *reinterpret_cast<uint2*>(Al + row * SSTR + c4 * 4) = lo;
            split_f4(regB[t], hi, lo);
            *reinterpret_cast<uint2*>(Bh + row * SSTR + c4 * 4) = hi;
            *reinterpret_cast<uint2*>(Bl + row * SSTR + c4 * 4) = lo;
        }
    }
    __syncthreads();

    for (int it = 0; it < ntile; it++) {
        if (it + 1 < ntile) {
            const int k0 = (it + 1) * GBK;
#pragma unroll
            for (int t = 0; t < 4; t++) {
                int idx = tid + 256 * t;
                int row = idx >> 3, c4 = idx & 7;
                regA[t] = *reinterpret_cast<const float4*>(A + (size_t)(bm + row) * K + k0 + c4 * 4);
                regB[t] = *reinterpret_cast<const float4*>(B + (size_t)(bn + row) * K + k0 + c4 * 4);
            }
        }
        {
            const __nv_bfloat16* base = sh + (it & 1) * BUF_H;
            const __nv_bfloat16* Ah = base;
            const __nv_bfloat16* Al = base + TILE_H;
            const __nv_bfloat16* Bh = base + 2 * TILE_H;
            const __nv_bfloat16* Bl = base + 3 * TILE_H;
#pragma unroll
            for (int ks = 0; ks < GBK; ks += 16) {
                AFrag a_h[4], a_l[4];
                BFrag b_h[2], b_l[2];
#pragma unroll
                for (int mi = 0; mi < 4; mi++) {
                    int r = (wm * 64 + mi * 16) * SSTR + ks;
                    wmma::load_matrix_sync(a_h[mi], Ah + r, SSTR);
                    wmma::load_matrix_sync(a_l[mi], Al + r, SSTR);
                }
#pragma unroll
                for (int ni = 0; ni < 2; ni++) {
                    int r = (wn * 32 + ni * 16) * SSTR + ks;
                    wmma::load_matrix_sync(b_h[ni], Bh + r, SSTR);
                    wmma::load_matrix_sync(b_l[ni], Bl + r, SSTR);
                }
#pragma unroll
                for (int mi = 0; mi < 4; mi++)
#pragma unroll
                    for (int ni = 0; ni < 2; ni++) {
                        wmma::mma_sync(c[mi][ni], a_h[mi], b_h[ni], c[mi][ni]);
                        wmma::mma_sync(c[mi][ni], a_h[mi], b_l[ni], c[mi][ni]);
                        wmma::mma_sync(c[mi][ni], a_l[mi], b_h[ni], c[mi][ni]);
                    }
            }
        }
        if (it + 1 < ntile) {
            __nv_bfloat16* base = sh + ((it + 1) & 1) * BUF_H;
            __nv_bfloat16* Ah = base;
            __nv_bfloat16* Al = base + TILE_H;
            __nv_bfloat16* Bh = base + 2 * TILE_H;
            __nv_bfloat16* Bl = base + 3 * TILE_H;
#pragma unroll
            for (int t = 0; t < 4; t++) {
                int idx = tid + 256 * t;
                int row = idx >> 3, c4 = idx & 7;
                uint2 hi, lo;
                split_f4(regA[t], hi, lo);
                *reinterpret_cast<uint2*>(Ah + row * SSTR + c4 * 4) = hi;
                *reinterpret_cast<uint2*>(Al + row * SSTR + c4 * 4) = lo;
                split_f4(regB[t], hi, lo);
                *reinterpret_cast<uint2*>(Bh + row * SSTR + c4 * 4) = hi;
                *reinterpret_cast<uint2*>(Bl + row * SSTR + c4 * 4) = lo;
            }
        }
        __syncthreads();
    }

#pragma unroll
    for (int mi = 0; mi < 4; mi++)
#pragma unroll
        for (int ni = 0; ni < 2; ni++) {
            int r = bm + wm * 64 + mi * 16;
            int cc = bn + wn * 32 + ni * 16;
            wmma::store_matrix_sync(C + (size_t)r * N + cc, c[mi][ni], N, wmma::mem_row_major);
        }
}

// =================================================================
// RoPE applied in place to Q and K.
// =================================================================
__global__ void rope_kernel(float* __restrict__ Q, float* __restrict__ K)
{
    int idx = blockIdx.x * blockDim.x + threadIdx.x;
    if (idx >= SEQ * (HIDDEN / 2)) return;
    int s    = idx / (HIDDEN / 2);
    int r    = idx % (HIDDEN / 2);
    int head = r / 64;
    int i    = r % 64;

    double e    = (double)(2 * i) / 128.0;
    float  finv = (float)pow(10000.0, -e);
    float  ang  = (float)s * finv;
    double sn, cs;
    sincos((double)ang, &sn, &cs);
    float c = (float)cs, sv = (float)sn;

    int base = s * HIDDEN + head * HDIM + i;
    {
        float x1 = Q[base], x2 = Q[base + 64];
        Q[base]      = x1 * c - x2 * sv;
        Q[base + 64] = x2 * c + x1 * sv;
    }
    {
        float x1 = K[base], x2 = K[base + 64];
        K[base]      = x1 * c - x2 * sv;
        K[base + 64] = x2 * c + x1 * sv;
    }
}

// =================================================================
// Tensor-core flash attention (mma.sync bf16x3, FA2-style).
// BQ=128 q-rows/CTA, BKEY=64 keys/iter, 256 threads (8 warps x 16 rows).
// Q,K: hi/lo bf16 row-major smem. V: hi/lo bf16 TRANSPOSED [dim][key].
// Strides: 136 halves (272B) and 72 halves (144B): both == 16 mod 128 B
// -> conflict-free ldmatrix.
// =================================================================
#define AQS 136
#define AVS 72
#define AOFF_QH 0
#define AOFF_QL 34816
#define AOFF_KH 69632
#define AOFF_KL 87040
#define AOFF_VH 104448
#define AOFF_VL 122880
#define ATTN_SMEM 141312

__global__ __launch_bounds__(256, 1) void attn_mma(const float* __restrict__ Q,
                                                   const float* __restrict__ K,
                                                   const float* __restrict__ V,
                                                   float* __restrict__ CTX)
{
    extern __shared__ char sm[];
    const uint32_t sb = smem_u32(sm);

    const int tid  = threadIdx.x;
    const int lane = tid & 31;
    const int wid  = tid >> 5;
    const int wq   = wid * 16;                       // warp's q-row base in tile
    const int qb   = 31 - (int)blockIdx.x;           // longest-first
    const int h    = blockIdx.y;
    const float scale = 0.08838834764831845f;        // 1/sqrt(128)

    // ---- Q tile load: 128 rows x 128 d, scaled, split hi/lo ----
    const float* Qg = Q + (size_t)(qb * 128) * HIDDEN + h * HDIM;
#pragma unroll
    for (int t = 0; t < 16; t++) {
        int idx = tid + 256 * t;
        int row = idx >> 5, c4 = idx & 31;
        float4 v = *reinterpret_cast<const float4*>(Qg + (size_t)row * HIDDEN + c4 * 4);
        v.x *= scale; v.y *= scale; v.z *= scale; v.w *= scale;
        uint2 hi, lo;
        split_f4(v, hi, lo);
        *reinterpret_cast<uint2*>(sm + AOFF_QH + row * (AQS * 2) + c4 * 8) = hi;
        *reinterpret_cast<uint2*>(sm + AOFF_QL + row * (AQS * 2) + c4 * 8) = lo;
    }

    // per-thread softmax state (rows r0 = wq + lane/4, r1 = r0 + 8)
    float m0 = -1e30f, m1 = -1e30f, l0 = 0.0f, l1 = 0.0f;
    float oacc[16][4];
#pragma unroll
    for (int n = 0; n < 16; n++)
#pragma unroll
        for (int j = 0; j < 4; j++) oacc[n][j] = 0.0f;

    // ldmatrix lane-address components
    const int aq_row  = wq + (lane & 15);
    const int aq_col  = (lane >> 4) * 8;
    const uint32_t aQh = sb + AOFF_QH + (aq_row * AQS + aq_col) * 2;
    const uint32_t aQl = sb + AOFF_QL + (aq_row * AQS + aq_col) * 2;

    const int b_row  = (lane & 7) + ((lane >> 4) << 3);   // +8 for lanes 16-31
    const int b_col  = ((lane >> 3) & 1) * 8;
    const uint32_t aKh = sb + AOFF_KH + (b_row * AQS + b_col) * 2;
    const uint32_t aKl = sb + AOFF_KL + (b_row * AQS + b_col) * 2;
    const uint32_t aVh = sb + AOFF_VH + (b_row * AVS + b_col) * 2;
    const uint32_t aVl = sb + AOFF_VL + (b_row * AVS + b_col) * 2;

    const int kb_max = 2 * qb + 1;
    for (int kb = 0; kb <= kb_max; kb++) {
        __syncthreads();   // previous iteration's reads done before refill

        // ---- K tile: 64 x 128, row-major hi/lo ----
        const float* Kg = K + (size_t)(kb * 64) * HIDDEN + h * HDIM;
        const float* Vg = V + (size_t)(kb * 64) * HIDDEN + h * HDIM;
#pragma unroll
        for (int t = 0; t < 8; t++) {
            int idx = tid + 256 * t;
            int row = idx >> 5, c4 = idx & 31;
            float4 v = *reinterpret_cast<const float4*>(Kg + (size_t)row * HIDDEN + c4 * 4);
            uint2 hi, lo;
            split_f4(v, hi, lo);
            *reinterpret_cast<uint2*>(sm + AOFF_KH + row * (AQS * 2) + c4 * 8) = hi;
            *reinterpret_cast<uint2*>(sm + AOFF_KL + row * (AQS * 2) + c4 * 8) = lo;
        }
        // ---- V tile: transpose to [dim][key], hi/lo ----
#pragma unroll
        for (int t = 0; t < 8; t++) {
            int idx = tid + 256 * t;
            int key = idx >> 5, c4 = idx & 31;
            float4 v = *reinterpret_cast<const float4*>(Vg + (size_t)key * HIDDEN + c4 * 4);
            float xs[4] = {v.x, v.y, v.z, v.w};
#pragma unroll
            for (int d = 0; d < 4; d++) {
                int dim = c4 * 4 + d;
                __nv_bfloat16 hb = __float2bfloat16_rn(xs[d]);
                __nv_bfloat16 lb = __float2bfloat16_rn(xs[d] - __bfloat162float(hb));
                *reinterpret_cast<__nv_bfloat16*>(sm + AOFF_VH + (dim * AVS + key) * 2) = hb;
                *reinterpret_cast<__nv_bfloat16*>(sm + AOFF_VL + (dim * AVS + key) * 2) = lb;
            }
        }
        __syncthreads();

        // ---- S = Q K^T : 8 n-tiles of 8 keys, fp32 accum ----
        float sacc[8][4];
#pragma unroll
        for (int n = 0; n < 8; n++)
#pragma unroll
            for (int j = 0; j < 4; j++) sacc[n][j] = 0.0f;

#pragma unroll
        for (int kk = 0; kk < 8; kk++) {
            uint32_t ah[4], al[4];
            LDM4(ah, aQh + kk * 32);
            LDM4(al, aQl + kk * 32);
#pragma unroll
            for (int np = 0; np < 4; np++) {
                uint32_t bh[4], bl[4];
                LDM4(bh, aKh + np * 16 * (AQS * 2) + kk * 32);
                LDM4(bl, aKl + np * 16 * (AQS * 2) + kk * 32);
                mma16816(sacc[2 * np],     ah, bh);
                mma16816(sacc[2 * np],     ah, bl);
                mma16816(sacc[2 * np],     al, bh);
                mma16816(sacc[2 * np + 1], ah, bh + 2);
                mma16816(sacc[2 * np + 1], ah, bl + 2);
                mma16816(sacc[2 * np + 1], al, bh + 2);
            }
        }

        // ---- causal mask (only diagonal blocks) ----
        if (kb >= 2 * qb) {
            int rowg0 = qb * 128 + wq + (lane >> 2);
            int rowg1 = rowg0 + 8;
            int colb  = kb * 64 + ((lane & 3) << 1);
#pragma unroll
            for (int n = 0; n < 8; n++) {
                int cg = colb + n * 8;
                if (cg     > rowg0) sacc[n][0] = -1e30f;
                if (cg + 1 > rowg0) sacc[n][1] = -1e30f;
                if (cg     > rowg1) sacc[n][2] = -1e30f;
                if (cg + 1 > rowg1) sacc[n][3] = -1e30f;
            }
        }

        // ---- online softmax (rows r0, r1; reduce over 4 lanes) ----
        float mx0 = -1e30f, mx1 = -1e30f;
#pragma unroll
        for (int n = 0; n < 8; n++) {
            mx0 = fmaxf(mx0, fmaxf(sacc[n][0], sacc[n][1]));
            mx1 = fmaxf(mx1, fmaxf(sacc[n][2], sacc[n][3]));
        }
        mx0 = fmaxf(mx0, __shfl_xor_sync(0xffffffffu, mx0, 1));
        mx0 = fmaxf(mx0, __shfl_xor_sync(0xffffffffu, mx0, 2));
        mx1 = fmaxf(mx1, __shfl_xor_sync(0xffffffffu, mx1, 1));
        mx1 = fmaxf(mx1, __shfl_xor_sync(0xffffffffu, mx1, 2));

        float mn0 = fmaxf(m0, mx0), mn1 = fmaxf(m1, mx1);
        float cr0 = __expf(m0 - mn0), cr1 = __expf(m1 - mn1);
        m0 = mn0; m1 = mn1;

        float sum0 = 0.0f, sum1 = 0.0f;
#pragma unroll
        for (int n = 0; n < 8; n++) {
            sacc[n][0] = __expf(sacc[n][0] - mn0);
            sacc[n][1] = __expf(sacc[n][1] - mn0);
            sacc[n][2] = __expf(sacc[n][2] - mn1);
            sacc[n][3] = __expf(sacc[n][3] - mn1);
            sum0 += sacc[n][0] + sacc[n][1];
            sum1 += sacc[n][2] + sacc[n][3];
        }
        sum0 += __shfl_xor_sync(0xffffffffu, sum0, 1);
        sum0 += __shfl_xor_sync(0xffffffffu, sum0, 2);
        sum1 += __shfl_xor_sync(0xffffffffu, sum1, 1);
        sum1 += __shfl_xor_sync(0xffffffffu, sum1, 2);
        l0 = l0 * cr0 + sum0;
        l1 = l1 * cr1 + sum1;

#pragma unroll
        for (int n = 0; n < 16; n++) {
            oacc[n][0] *= cr0; oacc[n][1] *= cr0;
            oacc[n][2] *= cr1; oacc[n][3] *= cr1;
        }

        // ---- O += P V : P from registers (S accum layout == A frag) ----
#pragma unroll
        for (int k2 = 0; k2 < 4; k2++) {
            uint32_t ph[4], pl[4];
            split_pack(sacc[2 * k2][0],     sacc[2 * k2][1],     ph[0], pl[0]);
            split_pack(sacc[2 * k2][2],     sacc[2 * k2][3],     ph[1], pl[1]);
            split_pack(sacc[2 * k2 + 1][0], sacc[2 * k2 + 1][1], ph[2], pl[2]);
            split_pack(sacc[2 * k2 + 1][2], sacc[2 * k2 + 1][3], ph[3], pl[3]);
#pragma unroll
            for (int np = 0; np < 8; np++) {
                uint32_t vh[4], vl[4];
                LDM4(vh, aVh + np * 16 * (AVS * 2) + k2 * 32);
                LDM4(vl, aVl + np * 16 * (AVS * 2) + k2 * 32);
                mma16816(oacc[2 * np],     ph, vh);
                mma16816(oacc[2 * np],     ph, vl);
                mma16816(oacc[2 * np],     pl, vh);
                mma16816(oacc[2 * np + 1], ph, vh + 2);
                mma16816(oacc[2 * np + 1], ph, vl + 2);
                mma16816(oacc[2 * np + 1], pl, vh + 2);
            }
        }
    }

    // ---- epilogue: normalize, store ----
    float inv0 = 1.0f / l0, inv1 = 1.0f / l1;
    int rowg0 = qb * 128 + wq + (lane >> 2);
    float* C0 = CTX + (size_t)rowg0 * HIDDEN + h * HDIM + ((lane & 3) << 1);
    float* C1 = C0 + 8 * HIDDEN;
#pragma unroll
    for (int n = 0; n < 16; n++) {
        *reinterpret_cast<float2*>(C0 + n * 8) = make_float2(oacc[n][0] * inv0, oacc[n][1] * inv0);
        *reinterpret_cast<float2*>(C1 + n * 8) = make_float2(oacc[n][2] * inv1, oacc[n][3] * inv1);
    }
}

// =================================================================
// Launcher
// =================================================================
extern "C" void kernel_launch(void* const* d_in, const int* in_sizes, int n_in,
                              void* d_out, int out_size)
{
    const float* X  = (const float*)d_in[0];
    const float* Wq = (const float*)d_in[1];
    const float* Wk = (const float*)d_in[2];
    const float* Wv = (const float*)d_in[3];
    const float* Wo = (const float*)d_in[4];
    float* out = (float*)d_out;

    float *q, *k, *v, *ctx;
    cudaGetSymbolAddress((void**)&q,   g_Q);
    cudaGetSymbolAddress((void**)&k,   g_K);
    cudaGetSymbolAddress((void**)&v,   g_V);
    cudaGetSymbolAddress((void**)&ctx, g_C);

    cudaFuncSetAttribute(gemm_wmma, cudaFuncAttributeMaxDynamicSharedMemorySize, GEMM_SMEM_BYTES);

    dim3 ggrid(HIDDEN / 128, SEQ / 128);
    gemm_wmma<<<ggrid, 256, GEMM_SMEM_BYTES>>>(X, Wq, q, SEQ, HIDDEN, HIDDEN);
    gemm_wmma<<<ggrid, 256, GEMM_SMEM_BYTES>>>(X, Wk, k, SEQ, HIDDEN, HIDDEN);
    gemm_wmma<<<ggrid, 256, GEMM_SMEM_BYTES>>>(X, Wv, v, SEQ, HIDDEN, HIDDEN);

    int rope_threads = SEQ * (HIDDEN / 2);
    rope_kernel<<<(rope_threads + 255) / 256, 256>>>(q, k);

    cudaFuncSetAttribute(attn_mma, cudaFuncAttributeMaxDynamicSharedMemorySize, ATTN_SMEM);
    dim3 agrid(SEQ / 128, NHEADS);   // (32, 16)
    attn_mma<<<agrid, 256, ATTN_SMEM>>>(q, k, v, ctx);

    gemm_wmma<<<ggrid, 256, GEMM_SMEM_BYTES>>>(ctx, Wo, out, SEQ, HIDDEN, HIDDEN);
}

// round 6
// speedup vs baseline: 2.5129x; 1.3474x over previous
#include <cuda_runtime.h>
#include <cuda_bf16.h>
#include <math.h>
#include <cstdint>

#define SEQ     4096
#define HIDDEN  2048
#define NHEADS  16
#define HDIM    128

// ---------------- scratch (no allocations allowed) ----------------
__device__ float g_Q[SEQ * HIDDEN];
__device__ float g_K[SEQ * HIDDEN];
__device__ float g_V[SEQ * HIDDEN];
__device__ float g_C[SEQ * HIDDEN];

__device__ __nv_bfloat16 g_Xh[SEQ * HIDDEN];
__device__ __nv_bfloat16 g_Xl[SEQ * HIDDEN];
__device__ __nv_bfloat16 g_Ch[SEQ * HIDDEN];
__device__ __nv_bfloat16 g_Cl[SEQ * HIDDEN];
__device__ __nv_bfloat16 g_Wqh[HIDDEN * HIDDEN];
__device__ __nv_bfloat16 g_Wql[HIDDEN * HIDDEN];
__device__ __nv_bfloat16 g_Wkh[HIDDEN * HIDDEN];
__device__ __nv_bfloat16 g_Wkl[HIDDEN * HIDDEN];
__device__ __nv_bfloat16 g_Wvh[HIDDEN * HIDDEN];
__device__ __nv_bfloat16 g_Wvl[HIDDEN * HIDDEN];
__device__ __nv_bfloat16 g_Woh[HIDDEN * HIDDEN];
__device__ __nv_bfloat16 g_Wol[HIDDEN * HIDDEN];

// =================================================================
// Common helpers
// =================================================================
__device__ __forceinline__ uint32_t smem_u32(const void* p) {
    uint32_t a;
    asm("{ .reg .u64 t; cvta.to.shared.u64 t, %1; cvt.u32.u64 %0, t; }" : "=r"(a) : "l"(p));
    return a;
}

#define LDM4(r, addr) \
    asm volatile("ldmatrix.sync.aligned.m8n8.x4.shared.b16 {%0,%1,%2,%3}, [%4];" \
        : "=r"((r)[0]), "=r"((r)[1]), "=r"((r)[2]), "=r"((r)[3]) : "r"(addr))

#define CP_ASYNC16(dst, src) \
    asm volatile("cp.async.cg.shared.global [%0], [%1], 16;" :: "r"(dst), "l"(src))

#define CP_COMMIT() asm volatile("cp.async.commit_group;" ::: "memory")
#define CP_WAIT0()  asm volatile("cp.async.wait_group 0;" ::: "memory")

__device__ __forceinline__ void mma16816(float* c, const uint32_t* a, const uint32_t* b) {
    asm volatile(
        "mma.sync.aligned.m16n8k16.row.col.f32.bf16.bf16.f32 "
        "{%0,%1,%2,%3}, {%4,%5,%6,%7}, {%8,%9}, {%0,%1,%2,%3};"
        : "+f"(c[0]), "+f"(c[1]), "+f"(c[2]), "+f"(c[3])
        : "r"(a[0]), "r"(a[1]), "r"(a[2]), "r"(a[3]), "r"(b[0]), "r"(b[1]));
}

// pack (x0,x1) -> bf16x2 hi, and residual bf16x2 lo
__device__ __forceinline__ void split_pack(float x0, float x1, uint32_t& h, uint32_t& l) {
    uint32_t hh, ll;
    asm("cvt.rn.bf16x2.f32 %0, %1, %2;" : "=r"(hh) : "f"(x1), "f"(x0));
    float h0 = __uint_as_float(hh << 16);
    float h1 = __uint_as_float(hh & 0xffff0000u);
    float r0 = x0 - h0, r1 = x1 - h1;
    asm("cvt.rn.bf16x2.f32 %0, %1, %2;" : "=r"(ll) : "f"(r1), "f"(r0));
    h = hh; l = ll;
}

__device__ __forceinline__ void split_f4(float4 v, uint2& hi, uint2& lo)
{
    __nv_bfloat16 hx = __float2bfloat16_rn(v.x);
    __nv_bfloat16 hy = __float2bfloat16_rn(v.y);
    __nv_bfloat16 hz = __float2bfloat16_rn(v.z);
    __nv_bfloat16 hw = __float2bfloat16_rn(v.w);
    __nv_bfloat16 lx = __float2bfloat16_rn(v.x - __bfloat162float(hx));
    __nv_bfloat16 ly = __float2bfloat16_rn(v.y - __bfloat162float(hy));
    __nv_bfloat16 lz = __float2bfloat16_rn(v.z - __bfloat162float(hz));
    __nv_bfloat16 lw = __float2bfloat16_rn(v.w - __bfloat162float(hw));
    __nv_bfloat162 h01 = __halves2bfloat162(hx, hy);
    __nv_bfloat162 h23 = __halves2bfloat162(hz, hw);
    __nv_bfloat162 l01 = __halves2bfloat162(lx, ly);
    __nv_bfloat162 l23 = __halves2bfloat162(lz, lw);
    hi = make_uint2(*(uint32_t*)&h01, *(uint32_t*)&h23);
    lo = make_uint2(*(uint32_t*)&l01, *(uint32_t*)&l23);
}

// =================================================================
// Split kernel: fp32 -> (hi, lo) bf16 matrices (done ONCE per matrix)
// =================================================================
__global__ void split_kernel(const float* __restrict__ src,
                             __nv_bfloat16* __restrict__ h,
                             __nv_bfloat16* __restrict__ l, int n4)
{
    int i = blockIdx.x * blockDim.x + threadIdx.x;
    if (i >= n4) return;
    float4 v = reinterpret_cast<const float4*>(src)[i];
    uint2 hi, lo;
    split_f4(v, hi, lo);
    reinterpret_cast<uint2*>(h)[i] = hi;
    reinterpret_cast<uint2*>(l)[i] = lo;
}

// =================================================================
// Raw mma.sync bf16x3 GEMM (NT) on pre-split inputs.
// C[M,N] = (Ah+Al)[M,K] * (Bh+Bl)[N,K]^T  (hh + hl + lh terms)
// 128x128 CTA tile, BK=32, 256 threads = 8 warps (2x4), warp 64x32.
// cp.async 16B chunks, 2-stage smem pipeline, ldmatrix stride 40h.
// =================================================================
#define GSTR    40                 // smem stride (halves); 80B rows
#define GT_TILE 10240              // 128 * 80 bytes per sub-tile
#define GT_STG  40960              // Ah+Al+Bh+Bl per stage
#define GSMEM   81920              // 2 stages

__global__ __launch_bounds__(256, 2) void gemm_mma(const __nv_bfloat16* __restrict__ Ah,
                                                   const __nv_bfloat16* __restrict__ Al,
                                                   const __nv_bfloat16* __restrict__ Bh,
                                                   const __nv_bfloat16* __restrict__ Bl,
                                                   float* __restrict__ C,
                                                   int M, int N, int K)
{
    extern __shared__ char smg[];
    const uint32_t sb = smem_u32(smg);

    const int tid  = threadIdx.x;
    const int lane = tid & 31;
    const int wid  = tid >> 5;
    const int wm   = wid & 1;
    const int wn   = wid >> 1;
    const int bm   = blockIdx.y * 128;
    const int bn   = blockIdx.x * 128;

    // per-tile global row bases (halves)
    const __nv_bfloat16* srcs[4] = {
        Ah + (size_t)bm * K, Al + (size_t)bm * K,
        Bh + (size_t)bn * K, Bl + (size_t)bn * K };

    // cp.async issue: 2048 x 16B chunks, 8 per thread
    auto issue = [&](int stage, int k0) {
#pragma unroll
        for (int j = 0; j < 8; j++) {
            int idx = tid + 256 * j;
            int t = idx >> 9;
            int r = (idx >> 2) & 127;
            int c = idx & 3;
            const __nv_bfloat16* src = srcs[t] + (size_t)r * K + k0 + c * 8;
            uint32_t dst = sb + stage * GT_STG + t * GT_TILE + r * 80 + c * 16;
            CP_ASYNC16(dst, src);
        }
    };

    float acc[4][4][4];
#pragma unroll
    for (int mi = 0; mi < 4; mi++)
#pragma unroll
        for (int ni = 0; ni < 4; ni++)
#pragma unroll
            for (int j = 0; j < 4; j++) acc[mi][ni][j] = 0.0f;

    // ldmatrix base addresses (constant per thread)
    const uint32_t aA0 = sb + ((wm * 64 + (lane & 15)) * GSTR + (lane >> 4) * 8) * 2;
    const uint32_t aB0 = sb + 2 * GT_TILE +
        ((wn * 32 + (lane & 7) + ((lane >> 4) << 3)) * GSTR + ((lane >> 3) & 1) * 8) * 2;

    const int ntile = K / 32;      // 64

    issue(0, 0);
    CP_COMMIT();

    for (int it = 0; it < ntile; it++) {
        CP_WAIT0();
        __syncthreads();
        if (it + 1 < ntile) {
            issue((it + 1) & 1, (it + 1) * 32);
            CP_COMMIT();
        }

        const uint32_t stg = (it & 1) * GT_STG;
#pragma unroll
        for (int kk = 0; kk < 2; kk++) {
            uint32_t bh[2][4], bl[2][4];
#pragma unroll
            for (int nt = 0; nt < 2; nt++) {
                LDM4(bh[nt], aB0 + stg + nt * 1280 + kk * 32);
                LDM4(bl[nt], aB0 + stg + GT_TILE + nt * 1280 + kk * 32);
            }
#pragma unroll
            for (int mi = 0; mi < 4; mi++) {
                uint32_t ah[4], al[4];
                LDM4(ah, aA0 + stg + mi * 1280 + kk * 32);
                LDM4(al, aA0 + stg + GT_TILE + mi * 1280 + kk * 32);
#pragma unroll
                for (int nt = 0; nt < 2; nt++) {
                    mma16816(acc[mi][2 * nt],     ah, bh[nt]);
                    mma16816(acc[mi][2 * nt],     ah, bl[nt]);
                    mma16816(acc[mi][2 * nt],     al, bh[nt]);
                    mma16816(acc[mi][2 * nt + 1], ah, bh[nt] + 2);
                    mma16816(acc[mi][2 * nt + 1], ah, bl[nt] + 2);
                    mma16816(acc[mi][2 * nt + 1], al, bh[nt] + 2);
                }
            }
        }
    }

    // epilogue
#pragma unroll
    for (int mi = 0; mi < 4; mi++) {
        int r0 = bm + wm * 64 + mi * 16 + (lane >> 2);
#pragma unroll
        for (int ni = 0; ni < 4; ni++) {
            int cc = bn + wn * 32 + ni * 8 + ((lane & 3) << 1);
            *reinterpret_cast<float2*>(C + (size_t)r0 * N + cc) =
                make_float2(acc[mi][ni][0], acc[mi][ni][1]);
            *reinterpret_cast<float2*>(C + (size_t)(r0 + 8) * N + cc) =
                make_float2(acc[mi][ni][2], acc[mi][ni][3]);
        }
    }
}

// =================================================================
// RoPE applied in place to Q and K.
// =================================================================
__global__ void rope_kernel(float* __restrict__ Q, float* __restrict__ K)
{
    int idx = blockIdx.x * blockDim.x + threadIdx.x;
    if (idx >= SEQ * (HIDDEN / 2)) return;
    int s    = idx / (HIDDEN / 2);
    int r    = idx % (HIDDEN / 2);
    int head = r / 64;
    int i    = r % 64;

    double e    = (double)(2 * i) / 128.0;
    float  finv = (float)pow(10000.0, -e);
    float  ang  = (float)s * finv;
    double sn, cs;
    sincos((double)ang, &sn, &cs);
    float c = (float)cs, sv = (float)sn;

    int base = s * HIDDEN + head * HDIM + i;
    {
        float x1 = Q[base], x2 = Q[base + 64];
        Q[base]      = x1 * c - x2 * sv;
        Q[base + 64] = x2 * c + x1 * sv;
    }
    {
        float x1 = K[base], x2 = K[base + 64];
        K[base]      = x1 * c - x2 * sv;
        K[base + 64] = x2 * c + x1 * sv;
    }
}

// =================================================================
// Tensor-core flash attention (mma.sync bf16x3, FA2-style) — R5 passing.
// =================================================================
#define AQS 136
#define AVS 72
#define AOFF_QH 0
#define AOFF_QL 34816
#define AOFF_KH 69632
#define AOFF_KL 87040
#define AOFF_VH 104448
#define AOFF_VL 122880
#define ATTN_SMEM 141312

__global__ __launch_bounds__(256, 1) void attn_mma(const float* __restrict__ Q,
                                                   const float* __restrict__ K,
                                                   const float* __restrict__ V,
                                                   float* __restrict__ CTX)
{
    extern __shared__ char sm[];
    const uint32_t sb = smem_u32(sm);

    const int tid  = threadIdx.x;
    const int lane = tid & 31;
    const int wid  = tid >> 5;
    const int wq   = wid * 16;
    const int qb   = 31 - (int)blockIdx.x;
    const int h    = blockIdx.y;
    const float scale = 0.08838834764831845f;

    const float* Qg = Q + (size_t)(qb * 128) * HIDDEN + h * HDIM;
#pragma unroll
    for (int t = 0; t < 16; t++) {
        int idx = tid + 256 * t;
        int row = idx >> 5, c4 = idx & 31;
        float4 v = *reinterpret_cast<const float4*>(Qg + (size_t)row * HIDDEN + c4 * 4);
        v.x *= scale; v.y *= scale; v.z *= scale; v.w *= scale;
        uint2 hi, lo;
        split_f4(v, hi, lo);
        *reinterpret_cast<uint2*>(sm + AOFF_QH + row * (AQS * 2) + c4 * 8) = hi;
        *reinterpret_cast<uint2*>(sm + AOFF_QL + row * (AQS * 2) + c4 * 8) = lo;
    }

    float m0 = -1e30f, m1 = -1e30f, l0 = 0.0f, l1 = 0.0f;
    float oacc[16][4];
#pragma unroll
    for (int n = 0; n < 16; n++)
#pragma unroll
        for (int j = 0; j < 4; j++) oacc[n][j] = 0.0f;

    const int aq_row  = wq + (lane & 15);
    const int aq_col  = (lane >> 4) * 8;
    const uint32_t aQh = sb + AOFF_QH + (aq_row * AQS + aq_col) * 2;
    const uint32_t aQl = sb + AOFF_QL + (aq_row * AQS + aq_col) * 2;

    const int b_row  = (lane & 7) + ((lane >> 4) << 3);
    const int b_col  = ((lane >> 3) & 1) * 8;
    const uint32_t aKh = sb + AOFF_KH + (b_row * AQS + b_col) * 2;
    const uint32_t aKl = sb + AOFF_KL + (b_row * AQS + b_col) * 2;
    const uint32_t aVh = sb + AOFF_VH + (b_row * AVS + b_col) * 2;
    const uint32_t aVl = sb + AOFF_VL + (b_row * AVS + b_col) * 2;

    const int kb_max = 2 * qb + 1;
    for (int kb = 0; kb <= kb_max; kb++) {
        __syncthreads();

        const float* Kg = K + (size_t)(kb * 64) * HIDDEN + h * HDIM;
        const float* Vg = V + (size_t)(kb * 64) * HIDDEN + h * HDIM;
#pragma unroll
        for (int t = 0; t < 8; t++) {
            int idx = tid + 256 * t;
            int row = idx >> 5, c4 = idx & 31;
            float4 v = *reinterpret_cast<const float4*>(Kg + (size_t)row * HIDDEN + c4 * 4);
            uint2 hi, lo;
            split_f4(v, hi, lo);
            *reinterpret_cast<uint2*>(sm + AOFF_KH + row * (AQS * 2) + c4 * 8) = hi;
            *reinterpret_cast<uint2*>(sm + AOFF_KL + row * (AQS * 2) + c4 * 8) = lo;
        }
#pragma unroll
        for (int t = 0; t < 8; t++) {
            int idx = tid + 256 * t;
            int key = idx >> 5, c4 = idx & 31;
            float4 v = *reinterpret_cast<const float4*>(Vg + (size_t)key * HIDDEN + c4 * 4);
            float xs[4] = {v.x, v.y, v.z, v.w};
#pragma unroll
            for (int d = 0; d < 4; d++) {
                int dim = c4 * 4 + d;
                __nv_bfloat16 hb = __float2bfloat16_rn(xs[d]);
                __nv_bfloat16 lb = __float2bfloat16_rn(xs[d] - __bfloat162float(hb));
                *reinterpret_cast<__nv_bfloat16*>(sm + AOFF_VH + (dim * AVS + key) * 2) = hb;
                *reinterpret_cast<__nv_bfloat16*>(sm + AOFF_VL + (dim * AVS + key) * 2) = lb;
            }
        }
        __syncthreads();

        float sacc[8][4];
#pragma unroll
        for (int n = 0; n < 8; n++)
#pragma unroll
            for (int j = 0; j < 4; j++) sacc[n][j] = 0.0f;

#pragma unroll
        for (int kk = 0; kk < 8; kk++) {
            uint32_t ah[4], al[4];
            LDM4(ah, aQh + kk * 32);
            LDM4(al, aQl + kk * 32);
#pragma unroll
            for (int np = 0; np < 4; np++) {
                uint32_t bh[4], bl[4];
                LDM4(bh, aKh + np * 16 * (AQS * 2) + kk * 32);
                LDM4(bl, aKl + np * 16 * (AQS * 2) + kk * 32);
                mma16816(sacc[2 * np],     ah, bh);
                mma16816(sacc[2 * np],     ah, bl);
                mma16816(sacc[2 * np],     al, bh);
                mma16816(sacc[2 * np + 1], ah, bh + 2);
                mma16816(sacc[2 * np + 1], ah, bl + 2);
                mma16816(sacc[2 * np + 1], al, bh + 2);
            }
        }

        if (kb >= 2 * qb) {
            int rowg0 = qb * 128 + wq + (lane >> 2);
            int rowg1 = rowg0 + 8;
            int colb  = kb * 64 + ((lane & 3) << 1);
#pragma unroll
            for (int n = 0; n < 8; n++) {
                int cg = colb + n * 8;
                if (cg     > rowg0) sacc[n][0] = -1e30f;
                if (cg + 1 > rowg0) sacc[n][1] = -1e30f;
                if (cg     > rowg1) sacc[n][2] = -1e30f;
                if (cg + 1 > rowg1) sacc[n][3] = -1e30f;
            }
        }

        float mx0 = -1e30f, mx1 = -1e30f;
#pragma unroll
        for (int n = 0; n < 8; n++) {
            mx0 = fmaxf(mx0, fmaxf(sacc[n][0], sacc[n][1]));
            mx1 = fmaxf(mx1, fmaxf(sacc[n][2], sacc[n][3]));
        }
        mx0 = fmaxf(mx0, __shfl_xor_sync(0xffffffffu, mx0, 1));
        mx0 = fmaxf(mx0, __shfl_xor_sync(0xffffffffu, mx0, 2));
        mx1 = fmaxf(mx1, __shfl_xor_sync(0xffffffffu, mx1, 1));
        mx1 = fmaxf(mx1, __shfl_xor_sync(0xffffffffu, mx1, 2));

        float mn0 = fmaxf(m0, mx0), mn1 = fmaxf(m1, mx1);
        float cr0 = __expf(m0 - mn0), cr1 = __expf(m1 - mn1);
        m0 = mn0; m1 = mn1;

        float sum0 = 0.0f, sum1 = 0.0f;
#pragma unroll
        for (int n = 0; n < 8; n++) {
            sacc[n][0] = __expf(sacc[n][0] - mn0);
            sacc[n][1] = __expf(sacc[n][1] - mn0);
            sacc[n][2] = __expf(sacc[n][2] - mn1);
            sacc[n][3] = __expf(sacc[n][3] - mn1);
            sum0 += sacc[n][0] + sacc[n][1];
            sum1 += sacc[n][2] + sacc[n][3];
        }
        sum0 += __shfl_xor_sync(0xffffffffu, sum0, 1);
        sum0 += __shfl_xor_sync(0xffffffffu, sum0, 2);
        sum1 += __shfl_xor_sync(0xffffffffu, sum1, 1);
        sum1 += __shfl_xor_sync(0xffffffffu, sum1, 2);
        l0 = l0 * cr0 + sum0;
        l1 = l1 * cr1 + sum1;

#pragma unroll
        for (int n = 0; n < 16; n++) {
            oacc[n][0] *= cr0; oacc[n][1] *= cr0;
            oacc[n][2] *= cr1; oacc[n][3] *= cr1;
        }

#pragma unroll
        for (int k2 = 0; k2 < 4; k2++) {
            uint32_t ph[4], pl[4];
            split_pack(sacc[2 * k2][0],     sacc[2 * k2][1],     ph[0], pl[0]);
            split_pack(sacc[2 * k2][2],     sacc[2 * k2][3],     ph[1], pl[1]);
            split_pack(sacc[2 * k2 + 1][0], sacc[2 * k2 + 1][1], ph[2], pl[2]);
            split_pack(sacc[2 * k2 + 1][2], sacc[2 * k2 + 1][3], ph[3], pl[3]);
#pragma unroll
            for (int np = 0; np < 8; np++) {
                uint32_t vh[4], vl[4];
                LDM4(vh, aVh + np * 16 * (AVS * 2) + k2 * 32);
                LDM4(vl, aVl + np * 16 * (AVS * 2) + k2 * 32);
                mma16816(oacc[2 * np],     ph, vh);
                mma16816(oacc[2 * np],     ph, vl);
                mma16816(oacc[2 * np],     pl, vh);
                mma16816(oacc[2 * np + 1], ph, vh + 2);
                mma16816(oacc[2 * np + 1], ph, vl + 2);
                mma16816(oacc[2 * np + 1], pl, vh + 2);
            }
        }
    }

    float inv0 = 1.0f / l0, inv1 = 1.0f / l1;
    int rowg0 = qb * 128 + wq + (lane >> 2);
    float* C0 = CTX + (size_t)rowg0 * HIDDEN + h * HDIM + ((lane & 3) << 1);
    float* C1 = C0 + 8 * HIDDEN;
#pragma unroll
    for (int n = 0; n < 16; n++) {
        *reinterpret_cast<float2*>(C0 + n * 8) = make_float2(oacc[n][0] * inv0, oacc[n][1] * inv0);
        *reinterpret_cast<float2*>(C1 + n * 8) = make_float2(oacc[n][2] * inv1, oacc[n][3] * inv1);
    }
}

// =================================================================
// Launcher
// =================================================================
extern "C" void kernel_launch(void* const* d_in, const int* in_sizes, int n_in,
                              void* d_out, int out_size)
{
    const float* X  = (const float*)d_in[0];
    const float* Wq = (const float*)d_in[1];
    const float* Wk = (const float*)d_in[2];
    const float* Wv = (const float*)d_in[3];
    const float* Wo = (const float*)d_in[4];
    float* out = (float*)d_out;

    float *q, *k, *v, *ctx;
    cudaGetSymbolAddress((void**)&q,   g_Q);
    cudaGetSymbolAddress((void**)&k,   g_K);
    cudaGetSymbolAddress((void**)&v,   g_V);
    cudaGetSymbolAddress((void**)&ctx, g_C);

    __nv_bfloat16 *xh, *xl, *ch, *cl;
    __nv_bfloat16 *wqh, *wql, *wkh, *wkl, *wvh, *wvl, *woh, *wol;
    cudaGetSymbolAddress((void**)&xh,  g_Xh);  cudaGetSymbolAddress((void**)&xl,  g_Xl);
    cudaGetSymbolAddress((void**)&ch,  g_Ch);  cudaGetSymbolAddress((void**)&cl,  g_Cl);
    cudaGetSymbolAddress((void**)&wqh, g_Wqh); cudaGetSymbolAddress((void**)&wql, g_Wql);
    cudaGetSymbolAddress((void**)&wkh, g_Wkh); cudaGetSymbolAddress((void**)&wkl, g_Wkl);
    cudaGetSymbolAddress((void**)&wvh, g_Wvh); cudaGetSymbolAddress((void**)&wvl, g_Wvl);
    cudaGetSymbolAddress((void**)&woh, g_Woh); cudaGetSymbolAddress((void**)&wol, g_Wol);

    const int nX4 = SEQ * HIDDEN / 4;       // 2,097,152
    const int nW4 = HIDDEN * HIDDEN / 4;    // 1,048,576

    split_kernel<<<nX4 / 256, 256>>>(X,  xh,  xl,  nX4);
    split_kernel<<<nW4 / 256, 256>>>(Wq, wqh, wql, nW4);
    split_kernel<<<nW4 / 256, 256>>>(Wk, wkh, wkl, nW4);
    split_kernel<<<nW4 / 256, 256>>>(Wv, wvh, wvl, nW4);
    split_kernel<<<nW4 / 256, 256>>>(Wo, woh, wol, nW4);

    cudaFuncSetAttribute(gemm_mma, cudaFuncAttributeMaxDynamicSharedMemorySize, GSMEM);

    dim3 ggrid(HIDDEN / 128, SEQ / 128);    // (16, 32)
    gemm_mma<<<ggrid, 256, GSMEM>>>(xh, xl, wqh, wql, q, SEQ, HIDDEN, HIDDEN);
    gemm_mma<<<ggrid, 256, GSMEM>>>(xh, xl, wkh, wkl, k, SEQ, HIDDEN, HIDDEN);
    gemm_mma<<<ggrid, 256, GSMEM>>>(xh, xl, wvh, wvl, v, SEQ, HIDDEN, HIDDEN);

    int rope_threads = SEQ * (HIDDEN / 2);
    rope_kernel<<<(rope_threads + 255) / 256, 256>>>(q, k);

    cudaFuncSetAttribute(attn_mma, cudaFuncAttributeMaxDynamicSharedMemorySize, ATTN_SMEM);
    dim3 agrid(SEQ / 128, NHEADS);          // (32, 16)
    attn_mma<<<agrid, 256, ATTN_SMEM>>>(q, k, v, ctx);

    split_kernel<<<nX4 / 256, 256>>>(ctx, ch, cl, nX4);
    gemm_mma<<<ggrid, 256, GSMEM>>>(ch, cl, woh, wol, out, SEQ, HIDDEN, HIDDEN);
}